// round 8
// baseline (speedup 1.0000x reference)
#include <cuda_runtime.h>
#include <math.h>

#define NN   65536
#define DEG  16
#define NG   1024
#define NE   (NN*DEG)
#define PIT  68

typedef unsigned long long u64;

__device__ __align__(16) float g_bufA[NN*64];
__device__ __align__(16) float g_bufB[NN*64];
__device__ unsigned char g_lsrc[NE];
__device__ __align__(16) float g_psum[NG*64];
__device__ __align__(16) float g_psq [NG*64];
__device__ float g_scale[5][64];
__device__ float g_shift[5][64];

static __device__ __forceinline__ u64 f2fma(u64 a, u64 b, u64 c){
  u64 d; asm("fma.rn.f32x2 %0, %1, %2, %3;" : "=l"(d) : "l"(a), "l"(b), "l"(c)); return d;
}
static __device__ __forceinline__ u64 f2add(u64 a, u64 b){
  u64 d; asm("add.rn.f32x2 %0, %1, %2;" : "=l"(d) : "l"(a), "l"(b)); return d;
}
static __device__ __forceinline__ u64 f2mul(u64 a, u64 b){
  u64 d; asm("mul.rn.f32x2 %0, %1, %2;" : "=l"(d) : "l"(a), "l"(b)); return d;
}
static __device__ __forceinline__ u64 f2pack(float x, float y){
  u64 d; asm("mov.b64 %0, {%1,%2};" : "=l"(d) : "f"(x), "f"(y)); return d;
}
static __device__ __forceinline__ float f2lo(u64 a){ return __uint_as_float((unsigned)a); }
static __device__ __forceinline__ float f2hi(u64 a){ return __uint_as_float((unsigned)(a>>32)); }

static __device__ __forceinline__ float4 f4min(float4 a, float4 b){
  return make_float4(fminf(a.x,b.x),fminf(a.y,b.y),fminf(a.z,b.z),fminf(a.w,b.w));
}

__global__ void k_init(const int* __restrict__ src){
  int i = blockIdx.x*blockDim.x + threadIdx.x;
  if(i < NE) g_lsrc[i] = (unsigned char)(src[i] & 63);
}

// 64x64 GEMM piece: acc[i][j] += X[n0+i][:] . W[c4+16j][:], k-chunks of 4, f32x2.
static __device__ __forceinline__ void gemm16(u64 acc[4][4], const float* X, const float* W,
                                              int n0, int c4){
  #pragma unroll 2
  for(int ch=0;ch<16;ch++){
    ulonglong2 xv[4];
    #pragma unroll
    for(int i=0;i<4;i++) xv[i] = *(const ulonglong2*)(X + (n0+i)*PIT + 4*ch);
    #pragma unroll
    for(int j=0;j<4;j++){
      ulonglong2 wv = *(const ulonglong2*)(W + (c4+16*j)*PIT + 4*ch);
      #pragma unroll
      for(int i=0;i<4;i++){
        acc[i][j] = f2fma(xv[i].x, wv.x, acc[i][j]);
        acc[i][j] = f2fma(xv[i].y, wv.y, acc[i][j]);
      }
    }
  }
}

// =============== cheb layer 1: feat (N,16) -> pre-BN (N,64) ===============
__global__ __launch_bounds__(256,3) void k_cheb1(const float* __restrict__ feat,
                                                 const float* __restrict__ w,
                                                 const float* __restrict__ b){
  extern __shared__ float sm[];
  float* xs = sm;            // 64*20
  float* x1 = sm + 1280;
  float* x2 = sm + 2560;
  float* wt = sm + 3840;     // 64 rows pitch 52
  float* ys = sm + 7168;     // 64*68
  unsigned char* ls = (unsigned char*)(sm + 11520);
  const int g = blockIdx.x, t = threadIdx.x;

  for(int i=t;i<768;i+=256){
    int h = i & 63, kq = i >> 6;
    *(float4*)(wt + h*52 + 4*kq) = __ldg((const float4*)(w + h*48) + kq);
  }
  for(int i=t;i<256;i+=256){
    int nn = i>>2, j = i&3;
    *(float4*)(xs + nn*20 + 4*j) = __ldg((const float4*)(feat + (g*64+nn)*16) + j);
  }
  for(int i=t;i<1024;i+=256) ls[i] = g_lsrc[g*1024+i];
  __syncthreads();

  const int n = t>>2, q = t&3, c0 = 4*q;
  const unsigned char* lr = ls + n*16;
  const u64 cm16 = f2pack(-0.0625f,-0.0625f);
  const u64 c125 = f2pack(0.125f,0.125f);
  const u64 cm1  = f2pack(-1.f,-1.f);
  { u64 A0=0,A1=0;
    #pragma unroll
    for(int j=0;j<16;j++){
      ulonglong2 r = *(const ulonglong2*)(xs + (int)lr[j]*20 + c0);
      A0 = f2add(A0, r.x); A1 = f2add(A1, r.y);
    }
    ulonglong2 o; o.x = f2mul(A0, cm16); o.y = f2mul(A1, cm16);
    *(ulonglong2*)(x1 + n*20 + c0) = o; }
  __syncthreads();
  { u64 A0=0,A1=0;
    #pragma unroll
    for(int j=0;j<16;j++){
      ulonglong2 r = *(const ulonglong2*)(x1 + (int)lr[j]*20 + c0);
      A0 = f2add(A0, r.x); A1 = f2add(A1, r.y);
    }
    ulonglong2 X0 = *(const ulonglong2*)(xs + n*20 + c0);
    ulonglong2 o;
    o.x = f2mul(f2fma(A0, c125, X0.x), cm1);
    o.y = f2mul(f2fma(A1, c125, X0.y), cm1);
    *(ulonglong2*)(x2 + n*20 + c0) = o; }
  __syncthreads();

  const int c4 = t & 15, n0 = (t>>4)*4;
  u64 acc[4][4];
  #pragma unroll
  for(int i=0;i<4;i++)
    #pragma unroll
    for(int j=0;j<4;j++) acc[i][j] = 0ull;
  const float* bufs[3] = {xs, x1, x2};
  #pragma unroll
  for(int seg=0;seg<3;seg++){
    const float* X = bufs[seg];
    #pragma unroll
    for(int ch=0;ch<4;ch++){
      ulonglong2 xv[4];
      #pragma unroll
      for(int i=0;i<4;i++) xv[i] = *(const ulonglong2*)(X + (n0+i)*20 + 4*ch);
      #pragma unroll
      for(int j=0;j<4;j++){
        ulonglong2 wv = *(const ulonglong2*)(wt + (c4+16*j)*52 + seg*16 + 4*ch);
        #pragma unroll
        for(int i=0;i<4;i++){
          acc[i][j] = f2fma(xv[i].x, wv.x, acc[i][j]);
          acc[i][j] = f2fma(xv[i].y, wv.y, acc[i][j]);
        }
      }
    }
  }
  __syncthreads();
  float bj[4];
  #pragma unroll
  for(int j=0;j<4;j++) bj[j] = __ldg(b + c4 + 16*j);
  float* obase = g_bufA + (g*64+n0)*64;
  #pragma unroll
  for(int i=0;i<4;i++)
    #pragma unroll
    for(int j=0;j<4;j++){
      float v = f2lo(acc[i][j]) + f2hi(acc[i][j]) + bj[j];
      ys[(n0+i)*PIT + c4 + 16*j] = v;
      obase[i*64 + c4 + 16*j] = v;
    }
  __syncthreads();
  if(t < 64){
    float s=0.f, s2=0.f;
    for(int nn=0;nn<64;nn++){ float v = ys[nn*PIT + t]; s+=v; s2+=v*v; }
    g_psum[g*64+t]=s; g_psq[g*64+t]=s2;
  }
}

// =============== cheb layers 2/3: per-seg weight staging, 71KB smem ===============
// floats: xs 0  x1 4352  x2 8704  wt 13056  scs 17408 shs 17472  ls@17536
__global__ __launch_bounds__(256,3) void k_chebH(const float* __restrict__ w,
                                                 const float* __restrict__ b,
                                                 int si, const float* __restrict__ in,
                                                 float* __restrict__ out){
  extern __shared__ float sm[];
  float* xs  = sm;
  float* x1  = sm + 4352;
  float* x2  = sm + 8704;
  float* wt  = sm + 13056;
  float* scs = sm + 17408;
  float* shs = sm + 17472;
  unsigned char* ls = (unsigned char*)(sm + 17536);
  float* ys = x1;
  const int g = blockIdx.x, t = threadIdx.x;

  if(t < 64){ scs[t] = g_scale[si][t]; shs[t] = g_shift[si][t]; }
  // seg 0 weights: w[h][0..63] -> wt[h*68+..]
  for(int i=t;i<1024;i+=256){
    int h = i & 63, kq = i >> 6;
    *(float4*)(wt + h*68 + 4*kq) = __ldg((const float4*)(w + h*192) + kq);
  }
  for(int i=t;i<1024;i+=256) ls[i] = g_lsrc[g*1024+i];
  for(int i=t;i<1024;i+=256){
    int nn=i>>4, j=i&15, c=4*j;
    float4 v = __ldg((const float4*)(in + (g*64+nn)*64) + j);
    // scs/shs not yet sync'd -> do BN after sync below using raw store? No:
    // store raw, BN applied in a second loop after sync.
    *(float4*)(xs + nn*PIT + c) = v;
  }
  __syncthreads();
  // BN+ReLU in place
  for(int i=t;i<1024;i+=256){
    int nn=i>>4, j=i&15, c=4*j;
    float4 v = *(float4*)(xs + nn*PIT + c);
    v.x=fmaxf(fmaf(v.x,scs[c+0],shs[c+0]),0.f);
    v.y=fmaxf(fmaf(v.y,scs[c+1],shs[c+1]),0.f);
    v.z=fmaxf(fmaf(v.z,scs[c+2],shs[c+2]),0.f);
    v.w=fmaxf(fmaf(v.w,scs[c+3],shs[c+3]),0.f);
    *(float4*)(xs + nn*PIT + c) = v;
  }
  __syncthreads();

  const int n = t>>2, q = t&3, c0 = q*16;
  const int c4 = t & 15, n0 = (t>>4)*4;
  const unsigned char* lr = ls + n*16;
  const u64 cm16 = f2pack(-0.0625f,-0.0625f);
  const u64 c125 = f2pack(0.125f,0.125f);
  const u64 cm1  = f2pack(-1.f,-1.f);

  u64 acc[4][4];
  #pragma unroll
  for(int i=0;i<4;i++)
    #pragma unroll
    for(int j=0;j<4;j++) acc[i][j]=0ull;

  // --- window 1: x1 = lap(xs); GEMM0 (wt = W0, X = xs) ---
  { u64 A[8]={0,0,0,0,0,0,0,0};
    #pragma unroll
    for(int j=0;j<16;j++){
      const ulonglong2* r = (const ulonglong2*)(xs + (int)lr[j]*PIT + c0);
      #pragma unroll
      for(int m=0;m<4;m++){ ulonglong2 rv=r[m]; A[2*m]=f2add(A[2*m],rv.x); A[2*m+1]=f2add(A[2*m+1],rv.y); }
    }
    ulonglong2* o = (ulonglong2*)(x1 + n*PIT + c0);
    #pragma unroll
    for(int m=0;m<4;m++){ ulonglong2 ov; ov.x=f2mul(A[2*m],cm16); ov.y=f2mul(A[2*m+1],cm16); o[m]=ov; } }
  gemm16(acc, xs, wt, n0, c4);
  __syncthreads();          // x1 complete, GEMM0 done reading wt

  // --- window 2: load W1 -> wt; x2 = -2 lap(x1) - xs ---
  float4 wld[4];
  #pragma unroll
  for(int r=0;r<4;r++){
    int i = t + 256*r, h = i & 63, kq = i >> 6;
    wld[r] = __ldg((const float4*)(w + h*192 + 64) + kq);
  }
  { u64 A[8]={0,0,0,0,0,0,0,0};
    #pragma unroll
    for(int j=0;j<16;j++){
      const ulonglong2* r = (const ulonglong2*)(x1 + (int)lr[j]*PIT + c0);
      #pragma unroll
      for(int m=0;m<4;m++){ ulonglong2 rv=r[m]; A[2*m]=f2add(A[2*m],rv.x); A[2*m+1]=f2add(A[2*m+1],rv.y); }
    }
    const ulonglong2* xr = (const ulonglong2*)(xs + n*PIT + c0);
    ulonglong2* o = (ulonglong2*)(x2 + n*PIT + c0);
    #pragma unroll
    for(int m=0;m<4;m++){
      ulonglong2 xv = xr[m]; ulonglong2 ov;
      ov.x = f2mul(f2fma(A[2*m],   c125, xv.x), cm1);
      ov.y = f2mul(f2fma(A[2*m+1], c125, xv.y), cm1);
      o[m] = ov;
    } }
  #pragma unroll
  for(int r=0;r<4;r++){
    int i = t + 256*r, h = i & 63, kq = i >> 6;
    *(float4*)(wt + h*68 + 4*kq) = wld[r];
  }
  __syncthreads();

  // --- GEMM1 (wt = W1, X = x1) ---
  gemm16(acc, x1, wt, n0, c4);
  __syncthreads();

  // --- load W2; GEMM2 ---
  #pragma unroll
  for(int r=0;r<4;r++){
    int i = t + 256*r, h = i & 63, kq = i >> 6;
    *(float4*)(wt + h*68 + 4*kq) = __ldg((const float4*)(w + h*192 + 128) + kq);
  }
  __syncthreads();
  gemm16(acc, x2, wt, n0, c4);
  __syncthreads();          // all reads of x1 (=ys) long done; safe to overwrite

  float bj[4];
  #pragma unroll
  for(int j=0;j<4;j++) bj[j] = __ldg(b + c4 + 16*j);
  float* obase = out + (g*64+n0)*64;
  #pragma unroll
  for(int i=0;i<4;i++)
    #pragma unroll
    for(int j=0;j<4;j++){
      float v = f2lo(acc[i][j]) + f2hi(acc[i][j]) + bj[j];
      ys[(n0+i)*PIT + c4 + 16*j] = v;
      obase[i*64 + c4 + 16*j] = v;
    }
  __syncthreads();
  if(t < 64){
    float s=0.f, s2=0.f;
    for(int nn=0;nn<64;nn++){ float v = ys[nn*PIT + t]; s+=v; s2+=v*v; }
    g_psum[g*64+t]=s; g_psq[g*64+t]=s2;
  }
}

// =============== edge conv: split GEMMs, 71KB smem ===============
// floats: xs 0 (psum aliases)  wA 4352 (ys aliases)  wB 8704  ts 13056
//         scs 17408 shs 17472 cbs 17536  ls@17600
__global__ __launch_bounds__(256,3) void k_econv(const float* __restrict__ tw,
                                                 const float* __restrict__ tb,
                                                 const float* __restrict__ pw,
                                                 const float* __restrict__ pb,
                                                 int si, const float* __restrict__ in,
                                                 float* __restrict__ out){
  extern __shared__ float sm[];
  float* xs  = sm;          float* psum = sm;
  float* wA  = sm + 4352;   float* ys   = sm + 4352;
  float* wB  = sm + 8704;
  float* ts  = sm + 13056;
  float* scs = sm + 17408;
  float* shs = sm + 17472;
  float* cbs = sm + 17536;
  unsigned char* ls = (unsigned char*)(sm + 17600);
  const int g = blockIdx.x, t = threadIdx.x;

  if(t < 64){
    scs[t]=g_scale[si][t]; shs[t]=g_shift[si][t];
    cbs[t]=__ldg(tb+t)+__ldg(pb+t);
  }
  for(int i=t;i<1024;i+=256){
    int h = i & 63, kq = i >> 6;
    *(float4*)(wA + h*68 + 4*kq) = __ldg((const float4*)(tw + h*64) + kq);
    *(float4*)(wB + h*68 + 4*kq) = __ldg((const float4*)(pw + h*64) + kq);
  }
  for(int i=t;i<1024;i+=256) ls[i] = g_lsrc[g*1024+i];
  for(int i=t;i<1024;i+=256){
    int nn=i>>4, j=i&15;
    *(float4*)(xs + nn*PIT + 4*j) = __ldg((const float4*)(in + (g*64+nn)*64) + j);
  }
  __syncthreads();
  for(int i=t;i<1024;i+=256){
    int nn=i>>4, j=i&15, c=4*j;
    float4 v = *(float4*)(xs + nn*PIT + c);
    v.x=fmaxf(fmaf(v.x,scs[c+0],shs[c+0]),0.f);
    v.y=fmaxf(fmaf(v.y,scs[c+1],shs[c+1]),0.f);
    v.z=fmaxf(fmaf(v.z,scs[c+2],shs[c+2]),0.f);
    v.w=fmaxf(fmaf(v.w,scs[c+3],shs[c+3]),0.f);
    *(float4*)(xs + nn*PIT + c) = v;
  }
  __syncthreads();

  const int c4 = t & 15, n0 = (t>>4)*4;
  // pass 1: t = x @ twT -> ts
  { u64 ta[4][4];
    #pragma unroll
    for(int i=0;i<4;i++)
      #pragma unroll
      for(int j=0;j<4;j++) ta[i][j]=0ull;
    gemm16(ta, xs, wA, n0, c4);
    #pragma unroll
    for(int i=0;i<4;i++)
      #pragma unroll
      for(int j=0;j<4;j++)
        ts[(n0+i)*PIT + c4 + 16*j] = f2lo(ta[i][j]) + f2hi(ta[i][j]);
  }
  // pass 2: p = x @ pwT (regs), no sync needed (ts region fresh, xs/wB read-only)
  u64 pa[4][4];
  #pragma unroll
  for(int i=0;i<4;i++)
    #pragma unroll
    for(int j=0;j<4;j++) pa[i][j]=0ull;
  gemm16(pa, xs, wB, n0, c4);
  __syncthreads();     // everyone done reading xs -> psum may overwrite it
  #pragma unroll
  for(int i=0;i<4;i++)
    #pragma unroll
    for(int j=0;j<4;j++){
      int c = c4 + 16*j;
      psum[(n0+i)*PIT + c] = ts[(n0+i)*PIT + c] + f2lo(pa[i][j]) + f2hi(pa[i][j]) + cbs[c];
    }
  __syncthreads();

  // min over neighbors of ts; out = psum - min
  const int n = t>>2, q = t&3, c0 = q*16;
  const unsigned char* lr = ls + n*16;
  float4 mn[4];
  #pragma unroll
  for(int m=0;m<4;m++) mn[m]=make_float4(3e38f,3e38f,3e38f,3e38f);
  #pragma unroll
  for(int j=0;j<16;j++){
    const float4* r = (const float4*)(ts + (int)lr[j]*PIT + c0);
    #pragma unroll
    for(int m=0;m<4;m++) mn[m] = f4min(mn[m], r[m]);
  }
  float* orow = out + (g*64+n)*64;
  #pragma unroll
  for(int m=0;m<4;m++){
    float4 p = *(const float4*)(psum + n*PIT + c0 + 4*m);
    float4 ov = make_float4(p.x-mn[m].x, p.y-mn[m].y, p.z-mn[m].z, p.w-mn[m].w);
    *(float4*)(ys + n*PIT + c0 + 4*m) = ov;   // ys aliases wA (reads finished)
    *(float4*)(orow + c0 + 4*m) = ov;
  }
  __syncthreads();
  if(t < 64){
    float s=0.f, s2=0.f;
    for(int nn=0;nn<64;nn++){ float v = ys[nn*PIT + t]; s+=v; s2+=v*v; }
    g_psum[g*64+t]=s; g_psq[g*64+t]=s2;
  }
}

// ---------- BN stat finalize ----------
__global__ void k_final(const float* __restrict__ gam, const float* __restrict__ bet, int si){
  const int c = blockIdx.x, t = threadIdx.x;
  __shared__ float sa[256], sb[256];
  float s1=0.f, s2=0.f;
  for(int gg=t; gg<NG; gg+=256){ s1+=g_psum[gg*64+c]; s2+=g_psq[gg*64+c]; }
  sa[t]=s1; sb[t]=s2; __syncthreads();
  for(int o=128;o>0;o>>=1){ if(t<o){ sa[t]+=sa[t+o]; sb[t]+=sb[t+o]; } __syncthreads(); }
  if(t==0){
    float mu  = sa[0]*(1.f/(float)NN);
    float var = sb[0]*(1.f/(float)NN) - mu*mu;
    float sc  = __ldg(gam+c) * rsqrtf(var + 1e-5f);
    g_scale[si][c]=sc; g_shift[si][c]=__ldg(bet+c)-mu*sc;
  }
}

// ---------- final BN+ReLU + mean pool ----------
__global__ void k_pool(const float* __restrict__ in, float* __restrict__ out){
  const int g = blockIdx.x, h = threadIdx.x;
  const float sc = g_scale[4][h], sh = g_shift[4][h];
  float s = 0.f;
  for(int n=0;n<64;n++){
    float v = in[(g*64+n)*64 + h];
    s += fmaxf(fmaf(v,sc,sh), 0.f);
  }
  out[g*64+h] = s*(1.f/64.f);
}

extern "C" void kernel_launch(void* const* d_in, const int* in_sizes, int n_in,
                              void* d_out, int out_size){
  const float* feat = (const float*)d_in[0];
  const int*   src  = (const int*)d_in[1];
  const float *c1w=(const float*)d_in[4],  *c1b=(const float*)d_in[5];
  const float *bn1g=(const float*)d_in[6], *bn1b=(const float*)d_in[7];
  const float *e1tw=(const float*)d_in[8], *e1tb=(const float*)d_in[9];
  const float *e1pw=(const float*)d_in[10],*e1pb=(const float*)d_in[11];
  const float *bne1g=(const float*)d_in[12],*bne1b=(const float*)d_in[13];
  const float *c2w=(const float*)d_in[14], *c2b=(const float*)d_in[15];
  const float *bn2g=(const float*)d_in[16],*bn2b=(const float*)d_in[17];
  const float *e2tw=(const float*)d_in[18],*e2tb=(const float*)d_in[19];
  const float *e2pw=(const float*)d_in[20],*e2pb=(const float*)d_in[21];
  const float *bne2g=(const float*)d_in[22],*bne2b=(const float*)d_in[23];
  const float *c3w=(const float*)d_in[24], *c3b=(const float*)d_in[25];
  const float *bn3g=(const float*)d_in[26],*bn3b=(const float*)d_in[27];
  float* out = (float*)d_out;

  const int SM1 = 11776*4;
  const int SMH = 17800*4;
  const int SME = 17864*4;
  cudaFuncSetAttribute(k_cheb1, cudaFuncAttributeMaxDynamicSharedMemorySize, SM1);
  cudaFuncSetAttribute(k_chebH, cudaFuncAttributeMaxDynamicSharedMemorySize, SMH);
  cudaFuncSetAttribute(k_econv, cudaFuncAttributeMaxDynamicSharedMemorySize, SME);

  float *bufA, *bufB;
  cudaGetSymbolAddress((void**)&bufA, g_bufA);
  cudaGetSymbolAddress((void**)&bufB, g_bufB);

  k_init<<<(NE+255)/256, 256>>>(src);
  k_cheb1<<<NG, 256, SM1>>>(feat, c1w, c1b);
  k_final<<<64, 256>>>(bn1g, bn1b, 0);
  k_econv<<<NG, 256, SME>>>(e1tw, e1tb, e1pw, e1pb, 0, bufA, bufB);
  k_final<<<64, 256>>>(bne1g, bne1b, 1);
  k_chebH<<<NG, 256, SMH>>>(c2w, c2b, 1, bufB, bufA);
  k_final<<<64, 256>>>(bn2g, bn2b, 2);
  k_econv<<<NG, 256, SME>>>(e2tw, e2tb, e2pw, e2pb, 2, bufA, bufB);
  k_final<<<64, 256>>>(bne2g, bne2b, 3);
  k_chebH<<<NG, 256, SMH>>>(c3w, c3b, 3, bufB, bufA);
  k_final<<<64, 256>>>(bn3g, bn3b, 4);
  k_pool<<<NG, 64>>>(bufA, out);
}

// round 9
// speedup vs baseline: 1.0426x; 1.0426x over previous
#include <cuda_runtime.h>
#include <math.h>

#define NN   65536
#define NG   1024
#define PIT  68

typedef unsigned long long u64;

__device__ __align__(16) float g_bufA[NN*64];
__device__ __align__(16) float g_bufB[NN*64];
__device__ __align__(16) float g_psum[NG*64];
__device__ __align__(16) float g_psq [NG*64];
__device__ float g_scale[5][64];
__device__ float g_shift[5][64];

static __device__ __forceinline__ u64 f2fma(u64 a, u64 b, u64 c){
  u64 d; asm("fma.rn.f32x2 %0, %1, %2, %3;" : "=l"(d) : "l"(a), "l"(b), "l"(c)); return d;
}
static __device__ __forceinline__ u64 f2add(u64 a, u64 b){
  u64 d; asm("add.rn.f32x2 %0, %1, %2;" : "=l"(d) : "l"(a), "l"(b)); return d;
}
static __device__ __forceinline__ u64 f2mul(u64 a, u64 b){
  u64 d; asm("mul.rn.f32x2 %0, %1, %2;" : "=l"(d) : "l"(a), "l"(b)); return d;
}
static __device__ __forceinline__ u64 f2pack(float x, float y){
  u64 d; asm("mov.b64 %0, {%1,%2};" : "=l"(d) : "f"(x), "f"(y)); return d;
}
static __device__ __forceinline__ float f2lo(u64 a){ return __uint_as_float((unsigned)a); }
static __device__ __forceinline__ float f2hi(u64 a){ return __uint_as_float((unsigned)(a>>32)); }

static __device__ __forceinline__ float4 f4min(float4 a, float4 b){
  return make_float4(fminf(a.x,b.x),fminf(a.y,b.y),fminf(a.z,b.z),fminf(a.w,b.w));
}

// ---- balanced W-GEMM: out[dn+4i][cw+8r] += X[n][k].W[c][k], f32x2 over k ----
// warp tile 16 nodes x 32 channels. dn = a*16+(lane>>3), cw = b*32+(lane&7).
static __device__ __forceinline__ void bgemmW(u64 acc[4][4], const float* X, const float* W,
                                              int dn, int cw){
  #pragma unroll 2
  for(int ch=0;ch<16;ch++){
    ulonglong2 xv[4], wv[4];
    #pragma unroll
    for(int i=0;i<4;i++) xv[i] = *(const ulonglong2*)(X + (dn+4*i)*PIT + 4*ch);
    #pragma unroll
    for(int r=0;r<4;r++) wv[r] = *(const ulonglong2*)(W + (cw+8*r)*PIT + 4*ch);
    #pragma unroll
    for(int i=0;i<4;i++)
      #pragma unroll
      for(int r=0;r<4;r++){
        acc[i][r]=f2fma(xv[i].x, wv[r].x, acc[i][r]);
        acc[i][r]=f2fma(xv[i].y, wv[r].y, acc[i][r]);
      }
  }
}

// ---- balanced S-GEMM: out[dn+4i][cs..cs+3] += S[d][s].X[s][c], f32x2 over c ----
// acc[i][0] = channels (cs,cs+1), acc[i][1] = (cs+2,cs+3); pairs ARE outputs.
static __device__ __forceinline__ void bgemmS(u64 acc[4][2], const float* S, const float* X,
                                              int dn, int cs){
  #pragma unroll 2
  for(int sc=0;sc<16;sc++){
    float av[4][4]; ulonglong2 bv[4];
    #pragma unroll
    for(int i=0;i<4;i++) *(float4*)av[i] = *(const float4*)(S + (dn+4*i)*PIT + 4*sc);
    #pragma unroll
    for(int u=0;u<4;u++) bv[u] = *(const ulonglong2*)(X + (4*sc+u)*PIT + cs);
    #pragma unroll
    for(int i=0;i<4;i++)
      #pragma unroll
      for(int u=0;u<4;u++){
        u64 p = f2pack(av[i][u], av[i][u]);
        acc[i][0]=f2fma(p, bv[u].x, acc[i][0]);
        acc[i][1]=f2fma(p, bv[u].y, acc[i][1]);
      }
  }
}

// =============== cheb layer 1: feat (N,16) -> pre-BN (N,64) ===============
__global__ __launch_bounds__(256,3) void k_cheb1(const float* __restrict__ feat,
                                                 const int* __restrict__ src,
                                                 const float* __restrict__ w,
                                                 const float* __restrict__ b){
  extern __shared__ float sm[];
  float* xs = sm;            // 64*20
  float* x1 = sm + 1280;
  float* x2 = sm + 2560;
  float* wt = sm + 3840;     // 64 rows pitch 52
  float* ys = sm + 7168;     // 64*68
  unsigned char* ls = (unsigned char*)(sm + 11520);
  const int g = blockIdx.x, t = threadIdx.x;

  for(int i=t;i<768;i+=256){
    int h = i & 63, kq = i >> 6;
    *(float4*)(wt + h*52 + 4*kq) = __ldg((const float4*)(w + h*48) + kq);
  }
  for(int i=t;i<256;i+=256){
    int nn = i>>2, j = i&3;
    *(float4*)(xs + nn*20 + 4*j) = __ldg((const float4*)(feat + (g*64+nn)*16) + j);
  }
  for(int i=t;i<1024;i+=256) ls[i] = (unsigned char)(__ldg(src + g*1024 + i) & 63);
  __syncthreads();

  const int n = t>>2, q = t&3, c0 = 4*q;
  const unsigned char* lr = ls + n*16;
  const u64 cm16 = f2pack(-0.0625f,-0.0625f);
  const u64 c125 = f2pack(0.125f,0.125f);
  const u64 cm1  = f2pack(-1.f,-1.f);
  { u64 A0=0,A1=0;
    #pragma unroll
    for(int j=0;j<16;j++){
      ulonglong2 r = *(const ulonglong2*)(xs + (int)lr[j]*20 + c0);
      A0 = f2add(A0, r.x); A1 = f2add(A1, r.y);
    }
    ulonglong2 o; o.x = f2mul(A0, cm16); o.y = f2mul(A1, cm16);
    *(ulonglong2*)(x1 + n*20 + c0) = o; }
  __syncthreads();
  { u64 A0=0,A1=0;
    #pragma unroll
    for(int j=0;j<16;j++){
      ulonglong2 r = *(const ulonglong2*)(x1 + (int)lr[j]*20 + c0);
      A0 = f2add(A0, r.x); A1 = f2add(A1, r.y);
    }
    ulonglong2 X0 = *(const ulonglong2*)(xs + n*20 + c0);
    ulonglong2 o;
    o.x = f2mul(f2fma(A0, c125, X0.x), cm1);
    o.y = f2mul(f2fma(A1, c125, X0.y), cm1);
    *(ulonglong2*)(x2 + n*20 + c0) = o; }
  __syncthreads();

  const int c4 = t & 15, n0 = (t>>4)*4;
  u64 acc[4][4];
  #pragma unroll
  for(int i=0;i<4;i++)
    #pragma unroll
    for(int j=0;j<4;j++) acc[i][j] = 0ull;
  const float* bufs[3] = {xs, x1, x2};
  #pragma unroll
  for(int seg=0;seg<3;seg++){
    const float* X = bufs[seg];
    #pragma unroll
    for(int ch=0;ch<4;ch++){
      ulonglong2 xv[4];
      #pragma unroll
      for(int i=0;i<4;i++) xv[i] = *(const ulonglong2*)(X + (n0+i)*20 + 4*ch);
      #pragma unroll
      for(int j=0;j<4;j++){
        ulonglong2 wv = *(const ulonglong2*)(wt + (c4+16*j)*52 + seg*16 + 4*ch);
        #pragma unroll
        for(int i=0;i<4;i++){
          acc[i][j] = f2fma(xv[i].x, wv.x, acc[i][j]);
          acc[i][j] = f2fma(xv[i].y, wv.y, acc[i][j]);
        }
      }
    }
  }
  __syncthreads();
  float bj[4];
  #pragma unroll
  for(int j=0;j<4;j++) bj[j] = __ldg(b + c4 + 16*j);
  float* obase = g_bufA + (g*64+n0)*64;
  #pragma unroll
  for(int i=0;i<4;i++)
    #pragma unroll
    for(int j=0;j<4;j++){
      float v = f2lo(acc[i][j]) + f2hi(acc[i][j]) + bj[j];
      ys[(n0+i)*PIT + c4 + 16*j] = v;
      obase[i*64 + c4 + 16*j] = v;
    }
  __syncthreads();
  if(t < 64){
    float s=0.f, s2=0.f;
    for(int nn=0;nn<64;nn++){ float v = ys[nn*PIT + t]; s+=v; s2+=v*v; }
    g_psum[g*64+t]=s; g_psq[g*64+t]=s2;
  }
}

// =============== cheb layers 2/3: laps as S-GEMMs ===============
// floats: xs 0  x1 4352  S 8704  wt 13056  scs 17408 shs 17472
__global__ __launch_bounds__(256,3) void k_chebH(const float* __restrict__ w,
                                                 const float* __restrict__ b,
                                                 int si, const int* __restrict__ src,
                                                 const float* __restrict__ in,
                                                 float* __restrict__ out){
  extern __shared__ float sm[];
  float* xs  = sm;
  float* x1  = sm + 4352;
  float* S   = sm + 8704;
  float* wt  = sm + 13056;
  float* scs = sm + 17408;
  float* shs = sm + 17472;
  float* ys  = x1;
  const int g = blockIdx.x, t = threadIdx.x;
  const int lane = t & 31, wp = t >> 5;
  const int dn = (wp>>1)*16 + (lane>>3);   // +4i strided nodes
  const int cs = (wp&1)*32 + (lane&7)*4;   // contiguous 4 channels (S-GEMM)
  const int cw = (wp&1)*32 + (lane&7);     // +8r strided channels (W-GEMM)

  if(t < 64){ scs[t] = g_scale[si][t]; shs[t] = g_shift[si][t]; }
  { float4 z = make_float4(0.f,0.f,0.f,0.f);
    for(int i=t;i<1088;i+=256) ((float4*)S)[i] = z; }
  for(int i=t;i<1024;i+=256){
    int nn=i>>4, j=i&15;
    *(float4*)(xs + nn*PIT + 4*j) = __ldg((const float4*)(in + (g*64+nn)*64) + j);
  }
  for(int i=t;i<1024;i+=256){
    int h=i&63, kq=i>>6;
    *(float4*)(wt + h*PIT + 4*kq) = __ldg((const float4*)(w + h*192) + kq);
  }
  __syncthreads();
  // BN+ReLU in place; build S = -(1/16) * adjacency-count
  for(int i=t;i<1024;i+=256){
    int nn=i>>4, j=i&15, c=4*j;
    float4 v = *(float4*)(xs + nn*PIT + c);
    v.x=fmaxf(fmaf(v.x,scs[c+0],shs[c+0]),0.f);
    v.y=fmaxf(fmaf(v.y,scs[c+1],shs[c+1]),0.f);
    v.z=fmaxf(fmaf(v.z,scs[c+2],shs[c+2]),0.f);
    v.w=fmaxf(fmaf(v.w,scs[c+3],shs[c+3]),0.f);
    *(float4*)(xs + nn*PIT + c) = v;
  }
  for(int i=t;i<1024;i+=256){
    int sl = __ldg(src + g*1024 + i) & 63;
    atomicAdd(S + (i>>4)*PIT + sl, -0.0625f);
  }
  __syncthreads();

  u64 aW[4][4];
  #pragma unroll
  for(int i=0;i<4;i++)
    #pragma unroll
    for(int r=0;r<4;r++) aW[i][r] = 0ull;

  // P2: W-GEMM seg0 on X0; x1 = S @ X0
  bgemmW(aW, xs, wt, dn, cw);
  { u64 aS[4][2] = {{0,0},{0,0},{0,0},{0,0}};
    bgemmS(aS, S, xs, dn, cs);
    #pragma unroll
    for(int i=0;i<4;i++){
      ulonglong2 o; o.x = aS[i][0]; o.y = aS[i][1];
      *(ulonglong2*)(x1 + (dn+4*i)*PIT + cs) = o;
    }
  }
  __syncthreads();
  // P3: wt <- W seg1
  for(int i=t;i<1024;i+=256){
    int h=i&63, kq=i>>6;
    *(float4*)(wt + h*PIT + 4*kq) = __ldg((const float4*)(w + h*192) + 16 + kq);
  }
  __syncthreads();
  // P4: W-GEMM seg1 on X1; x2 = 2*(S@X1) - X0 (stored back into xs)
  bgemmW(aW, x1, wt, dn, cw);
  { u64 aS[4][2] = {{0,0},{0,0},{0,0},{0,0}};
    bgemmS(aS, S, x1, dn, cs);
    const u64 two = f2pack(2.f,2.f), mone = f2pack(-1.f,-1.f);
    #pragma unroll
    for(int i=0;i<4;i++){
      ulonglong2 x0 = *(const ulonglong2*)(xs + (dn+4*i)*PIT + cs);
      ulonglong2 o;
      o.x = f2fma(two, aS[i][0], f2mul(x0.x, mone));
      o.y = f2fma(two, aS[i][1], f2mul(x0.y, mone));
      *(ulonglong2*)(xs + (dn+4*i)*PIT + cs) = o;
    }
  }
  __syncthreads();
  // P5: wt <- W seg2
  for(int i=t;i<1024;i+=256){
    int h=i&63, kq=i>>6;
    *(float4*)(wt + h*PIT + 4*kq) = __ldg((const float4*)(w + h*192) + 32 + kq);
  }
  __syncthreads();
  // P6: W-GEMM seg2 on X2 (in xs); epilogue into ys (= x1 region, free)
  bgemmW(aW, xs, wt, dn, cw);
  { float bj[4];
    #pragma unroll
    for(int r=0;r<4;r++) bj[r] = __ldg(b + cw + 8*r);
    #pragma unroll
    for(int i=0;i<4;i++)
      #pragma unroll
      for(int r=0;r<4;r++)
        ys[(dn+4*i)*PIT + cw + 8*r] = f2lo(aW[i][r]) + f2hi(aW[i][r]) + bj[r];
  }
  __syncthreads();
  // P7: stats + coalesced global store
  for(int i=t;i<1024;i+=256){
    int nn=i>>4, j=i&15;
    *(float4*)(out + (g*64+nn)*64 + 4*j) = *(const float4*)(ys + nn*PIT + 4*j);
  }
  if(t < 64){
    float s=0.f, s2=0.f;
    for(int nn=0;nn<64;nn++){ float v = ys[nn*PIT + t]; s+=v; s2+=v*v; }
    g_psum[g*64+t]=s; g_psq[g*64+t]=s2;
  }
}

// =============== edge conv: balanced GEMMs, gather-min ===============
// floats: xs 0 (psum aliases)  wA 4352 (ys aliases)  wB 8704  ts 13056
//         scs 17408 shs 17472 cbs 17536  ls@17600
__global__ __launch_bounds__(256,3) void k_econv(const float* __restrict__ tw,
                                                 const float* __restrict__ tb,
                                                 const float* __restrict__ pw,
                                                 const float* __restrict__ pb,
                                                 int si, const int* __restrict__ src,
                                                 const float* __restrict__ in,
                                                 float* __restrict__ out){
  extern __shared__ float sm[];
  float* xs  = sm;          float* psum = sm;
  float* wA  = sm + 4352;   float* ys   = sm + 4352;
  float* wB  = sm + 8704;
  float* ts  = sm + 13056;
  float* scs = sm + 17408;
  float* shs = sm + 17472;
  float* cbs = sm + 17536;
  unsigned char* ls = (unsigned char*)(sm + 17600);
  const int g = blockIdx.x, t = threadIdx.x;
  const int lane = t & 31, wp = t >> 5;
  const int dn = (wp>>1)*16 + (lane>>3);
  const int cw = (wp&1)*32 + (lane&7);

  if(t < 64){
    scs[t]=g_scale[si][t]; shs[t]=g_shift[si][t];
    cbs[t]=__ldg(tb+t)+__ldg(pb+t);
  }
  for(int i=t;i<1024;i+=256){
    int h = i & 63, kq = i >> 6;
    *(float4*)(wA + h*PIT + 4*kq) = __ldg((const float4*)(tw + h*64) + kq);
    *(float4*)(wB + h*PIT + 4*kq) = __ldg((const float4*)(pw + h*64) + kq);
  }
  for(int i=t;i<1024;i+=256) ls[i] = (unsigned char)(__ldg(src + g*1024 + i) & 63);
  for(int i=t;i<1024;i+=256){
    int nn=i>>4, j=i&15;
    *(float4*)(xs + nn*PIT + 4*j) = __ldg((const float4*)(in + (g*64+nn)*64) + j);
  }
  __syncthreads();
  for(int i=t;i<1024;i+=256){
    int nn=i>>4, j=i&15, c=4*j;
    float4 v = *(float4*)(xs + nn*PIT + c);
    v.x=fmaxf(fmaf(v.x,scs[c+0],shs[c+0]),0.f);
    v.y=fmaxf(fmaf(v.y,scs[c+1],shs[c+1]),0.f);
    v.z=fmaxf(fmaf(v.z,scs[c+2],shs[c+2]),0.f);
    v.w=fmaxf(fmaf(v.w,scs[c+3],shs[c+3]),0.f);
    *(float4*)(xs + nn*PIT + c) = v;
  }
  __syncthreads();

  // pass 1: t = x @ twT -> ts
  { u64 ta[4][4];
    #pragma unroll
    for(int i=0;i<4;i++)
      #pragma unroll
      for(int r=0;r<4;r++) ta[i][r]=0ull;
    bgemmW(ta, xs, wA, dn, cw);
    #pragma unroll
    for(int i=0;i<4;i++)
      #pragma unroll
      for(int r=0;r<4;r++)
        ts[(dn+4*i)*PIT + cw + 8*r] = f2lo(ta[i][r]) + f2hi(ta[i][r]);
  }
  // pass 2: p = x @ pwT (regs)
  u64 pa[4][4];
  #pragma unroll
  for(int i=0;i<4;i++)
    #pragma unroll
    for(int r=0;r<4;r++) pa[i][r]=0ull;
  bgemmW(pa, xs, wB, dn, cw);
  __syncthreads();     // xs consumed -> psum may overwrite
  #pragma unroll
  for(int i=0;i<4;i++)
    #pragma unroll
    for(int r=0;r<4;r++){
      int c = cw + 8*r, d = dn + 4*i;
      psum[d*PIT + c] = ts[d*PIT + c] + f2lo(pa[i][r]) + f2hi(pa[i][r]) + cbs[c];
    }
  __syncthreads();

  // min over neighbors of ts; out = psum - min
  const int n = t>>2, q = t&3, c0 = q*16;
  const unsigned char* lr = ls + n*16;
  float4 mn[4];
  #pragma unroll
  for(int m=0;m<4;m++) mn[m]=make_float4(3e38f,3e38f,3e38f,3e38f);
  #pragma unroll
  for(int j=0;j<16;j++){
    const float4* r = (const float4*)(ts + (int)lr[j]*PIT + c0);
    #pragma unroll
    for(int m=0;m<4;m++) mn[m] = f4min(mn[m], r[m]);
  }
  float* orow = out + (g*64+n)*64;
  #pragma unroll
  for(int m=0;m<4;m++){
    float4 p = *(const float4*)(psum + n*PIT + c0 + 4*m);
    float4 ov = make_float4(p.x-mn[m].x, p.y-mn[m].y, p.z-mn[m].z, p.w-mn[m].w);
    *(float4*)(ys + n*PIT + c0 + 4*m) = ov;
    *(float4*)(orow + c0 + 4*m) = ov;
  }
  __syncthreads();
  if(t < 64){
    float s=0.f, s2=0.f;
    for(int nn=0;nn<64;nn++){ float v = ys[nn*PIT + t]; s+=v; s2+=v*v; }
    g_psum[g*64+t]=s; g_psq[g*64+t]=s2;
  }
}

// ---------- BN stat finalize ----------
__global__ void k_final(const float* __restrict__ gam, const float* __restrict__ bet, int si){
  const int c = blockIdx.x, t = threadIdx.x;
  __shared__ float sa[256], sb[256];
  float s1=0.f, s2=0.f;
  for(int gg=t; gg<NG; gg+=256){ s1+=g_psum[gg*64+c]; s2+=g_psq[gg*64+c]; }
  sa[t]=s1; sb[t]=s2; __syncthreads();
  for(int o=128;o>0;o>>=1){ if(t<o){ sa[t]+=sa[t+o]; sb[t]+=sb[t+o]; } __syncthreads(); }
  if(t==0){
    float mu  = sa[0]*(1.f/(float)NN);
    float var = sb[0]*(1.f/(float)NN) - mu*mu;
    float sc  = __ldg(gam+c) * rsqrtf(var + 1e-5f);
    g_scale[si][c]=sc; g_shift[si][c]=__ldg(bet+c)-mu*sc;
  }
}

// ---------- final BN+ReLU + mean pool ----------
__global__ void k_pool(const float* __restrict__ in, float* __restrict__ out){
  const int g = blockIdx.x, h = threadIdx.x;
  const float sc = g_scale[4][h], sh = g_shift[4][h];
  float s = 0.f;
  for(int n=0;n<64;n++){
    float v = in[(g*64+n)*64 + h];
    s += fmaxf(fmaf(v,sc,sh), 0.f);
  }
  out[g*64+h] = s*(1.f/64.f);
}

extern "C" void kernel_launch(void* const* d_in, const int* in_sizes, int n_in,
                              void* d_out, int out_size){
  const float* feat = (const float*)d_in[0];
  const int*   src  = (const int*)d_in[1];
  const float *c1w=(const float*)d_in[4],  *c1b=(const float*)d_in[5];
  const float *bn1g=(const float*)d_in[6], *bn1b=(const float*)d_in[7];
  const float *e1tw=(const float*)d_in[8], *e1tb=(const float*)d_in[9];
  const float *e1pw=(const float*)d_in[10],*e1pb=(const float*)d_in[11];
  const float *bne1g=(const float*)d_in[12],*bne1b=(const float*)d_in[13];
  const float *c2w=(const float*)d_in[14], *c2b=(const float*)d_in[15];
  const float *bn2g=(const float*)d_in[16],*bn2b=(const float*)d_in[17];
  const float *e2tw=(const float*)d_in[18],*e2tb=(const float*)d_in[19];
  const float *e2pw=(const float*)d_in[20],*e2pb=(const float*)d_in[21];
  const float *bne2g=(const float*)d_in[22],*bne2b=(const float*)d_in[23];
  const float *c3w=(const float*)d_in[24], *c3b=(const float*)d_in[25];
  const float *bn3g=(const float*)d_in[26],*bn3b=(const float*)d_in[27];
  float* out = (float*)d_out;

  const int SM1 = 11776*4;
  const int SMH = 17544*4;
  const int SME = 17864*4;
  cudaFuncSetAttribute(k_cheb1, cudaFuncAttributeMaxDynamicSharedMemorySize, SM1);
  cudaFuncSetAttribute(k_chebH, cudaFuncAttributeMaxDynamicSharedMemorySize, SMH);
  cudaFuncSetAttribute(k_econv, cudaFuncAttributeMaxDynamicSharedMemorySize, SME);

  float *bufA, *bufB;
  cudaGetSymbolAddress((void**)&bufA, g_bufA);
  cudaGetSymbolAddress((void**)&bufB, g_bufB);

  k_cheb1<<<NG, 256, SM1>>>(feat, src, c1w, c1b);
  k_final<<<64, 256>>>(bn1g, bn1b, 0);
  k_econv<<<NG, 256, SME>>>(e1tw, e1tb, e1pw, e1pb, 0, src, bufA, bufB);
  k_final<<<64, 256>>>(bne1g, bne1b, 1);
  k_chebH<<<NG, 256, SMH>>>(c2w, c2b, 1, src, bufB, bufA);
  k_final<<<64, 256>>>(bn2g, bn2b, 2);
  k_econv<<<NG, 256, SME>>>(e2tw, e2tb, e2pw, e2pb, 2, src, bufA, bufB);
  k_final<<<64, 256>>>(bne2g, bne2b, 3);
  k_chebH<<<NG, 256, SMH>>>(c3w, c3b, 3, src, bufB, bufA);
  k_final<<<64, 256>>>(bn3g, bn3b, 4);
  k_pool<<<NG, 64>>>(bufA, out);
}